// round 1
// baseline (speedup 1.0000x reference)
#include <cuda_runtime.h>
#include <math.h>

// Problem constants
#define NP    2048      // number of pairs (B/2)
#define DFEAT 256       // feature dim
#define BM 128
#define BN 128
#define BK 8
#define TM 8
#define TN 8

// Scratch accumulators (allocation-free rule: __device__ globals)
__device__ float g_RowS[NP];   // sum over row p of exp(1+E[p,k]) with exclusion
__device__ float g_ColS[NP];   // sum over col p of exp(1+E[k,p]) with exclusion
__device__ float g_Dpos[NP];   // E[p,p]

// ---------------------------------------------------------------------------
// Kernel 1: zero the global accumulators (fresh every launch / graph replay)
// ---------------------------------------------------------------------------
__global__ void sml_zero_kernel() {
    int i = blockIdx.x * blockDim.x + threadIdx.x;
    if (i < NP) {
        g_RowS[i] = 0.0f;
        g_ColS[i] = 0.0f;
    }
}

// ---------------------------------------------------------------------------
// Kernel 2: E = X_even @ X_odd^T / 128, fused exp(1+E) row/col reduction.
// Tile: 128x128, K chunk 8, 256 threads, 8x8 per-thread microtile.
// A rows = X[2*(r0+r)], B rows = X[2*(c0+c)+1].
// Element (gr,gc):
//   row contribution to RowS[gr] unless gc == 2*gr+1
//   col contribution to ColS[gc] unless gr == 2*gc
//   diagonal -> Dpos[gr] = E
// ---------------------------------------------------------------------------
__global__ __launch_bounds__(256, 2)
void sml_gemm_exp_kernel(const float* __restrict__ X) {
    __shared__ float As[BK][BM];
    __shared__ float Bs[BK][BN];
    __shared__ float rsum[BM];
    __shared__ float csum[BN];

    const int tid = threadIdx.x;
    const int r0 = blockIdx.y * BM;
    const int c0 = blockIdx.x * BN;

    if (tid < BM) { rsum[tid] = 0.0f; csum[tid] = 0.0f; }

    const int rowg = (tid >> 4) * TM;   // 0..120
    const int colg = (tid & 15) * TN;   // 0..120

    float acc[TM][TN];
#pragma unroll
    for (int i = 0; i < TM; i++)
#pragma unroll
        for (int j = 0; j < TN; j++) acc[i][j] = 0.0f;

    // Loader mapping: each thread loads one float4 per matrix per K-chunk.
    const int lrow = tid >> 1;          // 0..127
    const int lcol = (tid & 1) * 4;     // 0 or 4

    const float* Aptr = X + (size_t)(2 * (r0 + lrow)) * DFEAT + lcol;
    const float* Bptr = X + (size_t)(2 * (c0 + lrow) + 1) * DFEAT + lcol;

    for (int k0 = 0; k0 < DFEAT; k0 += BK) {
        const float4 av = *(const float4*)(Aptr + k0);
        const float4 bv = *(const float4*)(Bptr + k0);
        __syncthreads();   // previous iteration's reads done
        As[lcol + 0][lrow] = av.x;
        As[lcol + 1][lrow] = av.y;
        As[lcol + 2][lrow] = av.z;
        As[lcol + 3][lrow] = av.w;
        Bs[lcol + 0][lrow] = bv.x;
        Bs[lcol + 1][lrow] = bv.y;
        Bs[lcol + 2][lrow] = bv.z;
        Bs[lcol + 3][lrow] = bv.w;
        __syncthreads();

#pragma unroll
        for (int k = 0; k < BK; k++) {
            float af[TM], bf[TN];
            float4 a0 = *(const float4*)&As[k][rowg];
            float4 a1 = *(const float4*)&As[k][rowg + 4];
            float4 b0 = *(const float4*)&Bs[k][colg];
            float4 b1 = *(const float4*)&Bs[k][colg + 4];
            af[0] = a0.x; af[1] = a0.y; af[2] = a0.z; af[3] = a0.w;
            af[4] = a1.x; af[5] = a1.y; af[6] = a1.z; af[7] = a1.w;
            bf[0] = b0.x; bf[1] = b0.y; bf[2] = b0.z; bf[3] = b0.w;
            bf[4] = b1.x; bf[5] = b1.y; bf[6] = b1.z; bf[7] = b1.w;
#pragma unroll
            for (int i = 0; i < TM; i++)
#pragma unroll
                for (int j = 0; j < TN; j++)
                    acc[i][j] = fmaf(af[i], bf[j], acc[i][j]);
        }
    }

    // Epilogue: exp + masked row/col partials
    float rpart[TM], cpart[TN];
#pragma unroll
    for (int i = 0; i < TM; i++) rpart[i] = 0.0f;
#pragma unroll
    for (int j = 0; j < TN; j++) cpart[j] = 0.0f;

#pragma unroll
    for (int i = 0; i < TM; i++) {
        const int gr = r0 + rowg + i;
#pragma unroll
        for (int j = 0; j < TN; j++) {
            const int gc = c0 + colg + j;
            const float e = acc[i][j] * (1.0f / 128.0f);
            const float x = __expf(1.0f + e);
            if (gc != 2 * gr + 1) rpart[i] += x;
            if (gr != 2 * gc)     cpart[j] += x;
            if (gr == gc)         g_Dpos[gr] = e;
        }
    }

    // Needs the earlier zero of rsum/csum to be visible: the K-loop executed
    // >=2 __syncthreads() after those writes, so it is.
#pragma unroll
    for (int i = 0; i < TM; i++) atomicAdd(&rsum[rowg + i], rpart[i]);
#pragma unroll
    for (int j = 0; j < TN; j++) atomicAdd(&csum[colg + j], cpart[j]);
    __syncthreads();

    if (tid < BM) {
        atomicAdd(&g_RowS[r0 + tid], rsum[tid]);
    } else {
        const int c = tid - BM;
        atomicAdd(&g_ColS[c0 + c], csum[c]);
    }
}

// ---------------------------------------------------------------------------
// Kernel 3: J = log(1e-8 + RowS + ColS) - Dpos ; out = sum(max(J,0)^2)/4096
// ---------------------------------------------------------------------------
__global__ void sml_finalize_kernel(float* __restrict__ out) {
    __shared__ float red[256];
    const int tid = threadIdx.x;
    float s = 0.0f;
    for (int p = tid; p < NP; p += 256) {
        const float J = logf(1e-8f + g_RowS[p] + g_ColS[p]) - g_Dpos[p];
        const float t = fmaxf(J, 0.0f);
        s += t * t;
    }
    red[tid] = s;
    __syncthreads();
    for (int off = 128; off > 0; off >>= 1) {
        if (tid < off) red[tid] += red[tid + off];
        __syncthreads();
    }
    if (tid == 0) out[0] = red[0] * (1.0f / 4096.0f);
}

// ---------------------------------------------------------------------------
extern "C" void kernel_launch(void* const* d_in, const int* in_sizes, int n_in,
                              void* d_out, int out_size) {
    const float* X = (const float*)d_in[0];
    float* out = (float*)d_out;

    sml_zero_kernel<<<(NP + 255) / 256, 256>>>();
    dim3 grid(NP / BN, NP / BM);   // 16 x 16 CTAs
    sml_gemm_exp_kernel<<<grid, 256>>>(X);
    sml_finalize_kernel<<<1, 256>>>(out);
}

// round 4
// speedup vs baseline: 3.2029x; 3.2029x over previous
#include <cuda_runtime.h>
#include <cuda_bf16.h>
#include <cstdint>
#include <math.h>

#define NP    2048
#define DFEAT 256
#define BT    128
#define NBLK  (NP / BT)        // 16

// smem tile: 128 rows x 264 bf16 (padded; 528 B/row)
#define ROWB   528
#define TILE_B (BT * ROWB)     // 67584 B
#define SM_A   0
#define SM_B   TILE_B
#define SM_RS  (2 * TILE_B)            // rsum[128] floats
#define SM_CS  (2 * TILE_B + 512)      // csum[128] floats
#define SMEM_TOTAL (2 * TILE_B + 1024) // 136192 B

// -------- device scratch (allocation-free rule) --------
__device__ __align__(16) __nv_bfloat16 g_Abf[NP * DFEAT];  // X[2p] rows
__device__ __align__(16) __nv_bfloat16 g_Bbf[NP * DFEAT];  // X[2p+1] rows
__device__ float g_RowP[NBLK][NP];
__device__ float g_ColP[NBLK][NP];
__device__ float g_Dpos[NP];

static __device__ __forceinline__ uint32_t smem_u32(const void* p) {
    return (uint32_t)__cvta_generic_to_shared((void*)p);
}

static __device__ __forceinline__ void ldsm_x4(uint32_t* r, uint32_t addr) {
    asm volatile("ldmatrix.sync.aligned.m8n8.x4.shared.b16 {%0,%1,%2,%3}, [%4];"
                 : "=r"(r[0]), "=r"(r[1]), "=r"(r[2]), "=r"(r[3]) : "r"(addr));
}

static __device__ __forceinline__ void mma16816(float* c, const uint32_t* a,
                                                const uint32_t* b) {
    asm volatile(
        "mma.sync.aligned.m16n8k16.row.col.f32.bf16.bf16.f32 "
        "{%0,%1,%2,%3}, {%4,%5,%6,%7}, {%8,%9}, {%0,%1,%2,%3};"
        : "+f"(c[0]), "+f"(c[1]), "+f"(c[2]), "+f"(c[3])
        : "r"(a[0]), "r"(a[1]), "r"(a[2]), "r"(a[3]), "r"(b[0]), "r"(b[1]));
}

// ---------------------------------------------------------------------------
// Kernel 1: fp32 -> bf16 conversion + even/odd row deinterleave.
// ---------------------------------------------------------------------------
__global__ void sml_convert(const float* __restrict__ X) {
    const int i = blockIdx.x * blockDim.x + threadIdx.x;   // float4 index
    const float4 v = ((const float4*)X)[i];
    const int row = i >> 6;
    const int k4  = i & 63;
    const int p   = row >> 1;
    __nv_bfloat162 lo = __float22bfloat162_rn(make_float2(v.x, v.y));
    __nv_bfloat162 hi = __float22bfloat162_rn(make_float2(v.z, v.w));
    __nv_bfloat16* dst = (row & 1) ? g_Bbf : g_Abf;
    uint2 packed;
    packed.x = *(uint32_t*)&lo;
    packed.y = *(uint32_t*)&hi;
    *(uint2*)&dst[p * DFEAT + k4 * 4] = packed;
}

// ---------------------------------------------------------------------------
// Kernel 2: E-tile = Aeven[by] . Bodd[bx]^T via mma.sync; fused exp epilogue.
// 256 threads = 8 warps (4M x 2N), warp tile 32x64.
// ---------------------------------------------------------------------------
__global__ __launch_bounds__(256, 1)
void sml_gemm(void) {
    extern __shared__ char smem[];
    const uint32_t sbase = smem_u32(smem);
    float* rsum = (float*)(smem + SM_RS);
    float* csum = (float*)(smem + SM_CS);

    const int tid = threadIdx.x;
    const int wid = tid >> 5;
    const int l   = tid & 31;
    const int wm  = wid & 3;      // 0..3 -> M band of 32
    const int wn  = wid >> 2;     // 0..1 -> N band of 64
    const int bx = blockIdx.x, by = blockIdx.y;
    const int r0 = by * BT, c0 = bx * BT;

    if (tid < 128) { rsum[tid] = 0.0f; csum[tid] = 0.0f; }

    // ---- load tiles (bf16) into padded smem ----
#pragma unroll
    for (int i = 0; i < 16; i++) {
        const int row  = i * 8 + wid;
        uint4 a = *(const uint4*)&g_Abf[(r0 + row) * DFEAT + l * 8];
        uint4 b = *(const uint4*)&g_Bbf[(c0 + row) * DFEAT + l * 8];
        *(uint4*)(smem + SM_A + row * ROWB + l * 16) = a;
        *(uint4*)(smem + SM_B + row * ROWB + l * 16) = b;
    }
    __syncthreads();

    // ---- per-lane ldmatrix address components ----
    const int a_row = (l & 7) + 8 * ((l >> 3) & 1);
    const int a_kb  = 16 * ((l >> 4) & 1);
    const int b_row = (l & 7) + 8 * ((l >> 4) & 1);
    const int b_kb  = 16 * ((l >> 3) & 1);

    const uint32_t aAddr0 = sbase + SM_A + (uint32_t)(wm * 32 + a_row) * ROWB + a_kb;
    const uint32_t bAddr0 = sbase + SM_B + (uint32_t)(wn * 64 + b_row) * ROWB + b_kb;

    float acc[2][8][4];
#pragma unroll
    for (int mt = 0; mt < 2; mt++)
#pragma unroll
        for (int nt = 0; nt < 8; nt++)
#pragma unroll
            for (int r = 0; r < 4; r++) acc[mt][nt][r] = 0.0f;

    // ---- mainloop over K ----
#pragma unroll
    for (int ks = 0; ks < 16; ks++) {
        const uint32_t koff = (uint32_t)ks * 32;   // 16 bf16 = 32B
        uint32_t a[2][4];
        ldsm_x4(a[0], aAddr0 + koff);
        ldsm_x4(a[1], aAddr0 + 16 * ROWB + koff);
        uint32_t b[8][2];
#pragma unroll
        for (int q = 0; q < 4; q++) {
            uint32_t t[4];
            ldsm_x4(t, bAddr0 + (uint32_t)(q * 16) * ROWB + koff);
            b[2 * q][0] = t[0];  b[2 * q][1] = t[1];
            b[2 * q + 1][0] = t[2];  b[2 * q + 1][1] = t[3];
        }
#pragma unroll
        for (int mt = 0; mt < 2; mt++)
#pragma unroll
            for (int nt = 0; nt < 8; nt++)
                mma16816(acc[mt][nt], a[mt], b[nt]);
    }

    // ---- epilogue: exp, masked row/col partials, Dpos ----
    float rowp[2][2];
    float colp[8][2];
#pragma unroll
    for (int mt = 0; mt < 2; mt++)
#pragma unroll
        for (int h = 0; h < 2; h++) rowp[mt][h] = 0.0f;
#pragma unroll
    for (int nt = 0; nt < 8; nt++)
#pragma unroll
        for (int j = 0; j < 2; j++) colp[nt][j] = 0.0f;

#pragma unroll
    for (int mt = 0; mt < 2; mt++) {
#pragma unroll
        for (int h = 0; h < 2; h++) {
            const int gr = r0 + wm * 32 + mt * 16 + h * 8 + (l >> 2);
            const int rexcl = 2 * gr + 1;
#pragma unroll
            for (int nt = 0; nt < 8; nt++) {
#pragma unroll
                for (int j = 0; j < 2; j++) {
                    const int gc = c0 + wn * 64 + nt * 8 + 2 * (l & 3) + j;
                    const float e = acc[mt][nt][2 * h + j] * (1.0f / 128.0f);
                    const float x = __expf(1.0f + e);
                    if (gc != rexcl)  rowp[mt][h] += x;
                    if (gr != 2 * gc) colp[nt][j] += x;
                    if (gr == gc)     g_Dpos[gr] = e;
                }
            }
        }
    }

    // row sums: reduce across the 4 lanes of each quad (same row)
#pragma unroll
    for (int mt = 0; mt < 2; mt++) {
#pragma unroll
        for (int h = 0; h < 2; h++) {
            float v = rowp[mt][h];
            v += __shfl_xor_sync(0xFFFFFFFFu, v, 1);
            v += __shfl_xor_sync(0xFFFFFFFFu, v, 2);
            if ((l & 3) == 0)
                atomicAdd(&rsum[wm * 32 + mt * 16 + h * 8 + (l >> 2)], v);
        }
    }
    // col sums: reduce across the 8 lanes sharing l&3 (same cols)
#pragma unroll
    for (int nt = 0; nt < 8; nt++) {
#pragma unroll
        for (int j = 0; j < 2; j++) {
            float v = colp[nt][j];
            v += __shfl_xor_sync(0xFFFFFFFFu, v, 4);
            v += __shfl_xor_sync(0xFFFFFFFFu, v, 8);
            v += __shfl_xor_sync(0xFFFFFFFFu, v, 16);
            if ((l >> 2) == 0)
                atomicAdd(&csum[wn * 64 + nt * 8 + 2 * (l & 3) + j], v);
        }
    }
    __syncthreads();

    if (tid < 128) {
        g_RowP[bx][r0 + tid] = rsum[tid];
    } else {
        g_ColP[by][c0 + tid - 128] = csum[tid - 128];
    }
}

// ---------------------------------------------------------------------------
// Kernel 3: finalize.
// ---------------------------------------------------------------------------
__global__ void sml_finalize(float* __restrict__ out) {
    __shared__ float red[1024];
    const int tid = threadIdx.x;
    float acc = 0.0f;
#pragma unroll
    for (int rep = 0; rep < 2; rep++) {
        const int p = tid + rep * 1024;
        float rs = 0.0f, cs = 0.0f;
#pragma unroll
        for (int s = 0; s < NBLK; s++) {
            rs += g_RowP[s][p];
            cs += g_ColP[s][p];
        }
        const float J = logf(1e-8f + rs + cs) - g_Dpos[p];
        const float t = fmaxf(J, 0.0f);
        acc += t * t;
    }
    red[tid] = acc;
    __syncthreads();
    for (int off = 512; off > 0; off >>= 1) {
        if (tid < off) red[tid] += red[tid + off];
        __syncthreads();
    }
    if (tid == 0) out[0] = red[0] * (1.0f / 4096.0f);
}

// ---------------------------------------------------------------------------
extern "C" void kernel_launch(void* const* d_in, const int* in_sizes, int n_in,
                              void* d_out, int out_size) {
    const float* X = (const float*)d_in[0];
    float* out = (float*)d_out;

    sml_convert<<<1024, 256>>>(X);

    cudaFuncSetAttribute(sml_gemm, cudaFuncAttributeMaxDynamicSharedMemorySize,
                         SMEM_TOTAL);
    dim3 grid(NBLK, NBLK);
    sml_gemm<<<grid, 256, SMEM_TOTAL>>>();

    sml_finalize<<<1, 1024>>>(out);
}

// round 5
// speedup vs baseline: 3.4986x; 1.0923x over previous
#include <cuda_runtime.h>
#include <cuda_bf16.h>
#include <cstdint>
#include <math.h>

#define NP    2048
#define DFEAT 256
#define BTM   128              // tile rows
#define BTN   256              // tile cols
#define NBX   (NP / BTN)       // 8
#define NBY   (NP / BTM)       // 16

// smem rows padded: 256 bf16 + 8 pad = 264 bf16 = 528 B
#define ROWB   528
#define A_B    (BTM * ROWB)            // 67584
#define B_B    (BTN * ROWB)            // 135168
#define SM_A   0
#define SM_B   A_B
#define SM_RS  (A_B + B_B)             // rsum[128]
#define SM_CS  (A_B + B_B + 512)       // csum[256]
#define SMEM_TOTAL (A_B + B_B + 512 + 1024)   // 204288 B

// -------- device scratch --------
__device__ __align__(16) __nv_bfloat16 g_Abf[NP * DFEAT];  // X[2p]
__device__ __align__(16) __nv_bfloat16 g_Bbf[NP * DFEAT];  // X[2p+1]
__device__ float g_RowP[NBX][NP];
__device__ float g_ColP[NBY][NP];
__device__ float g_Dpos[NP];

static __device__ __forceinline__ uint32_t smem_u32(const void* p) {
    return (uint32_t)__cvta_generic_to_shared((void*)p);
}

static __device__ __forceinline__ void ldsm_x4(uint32_t* r, uint32_t addr) {
    asm volatile("ldmatrix.sync.aligned.m8n8.x4.shared.b16 {%0,%1,%2,%3}, [%4];"
                 : "=r"(r[0]), "=r"(r[1]), "=r"(r[2]), "=r"(r[3]) : "r"(addr));
}

static __device__ __forceinline__ void mma16816(float* c, const uint32_t* a,
                                                const uint32_t* b) {
    asm volatile(
        "mma.sync.aligned.m16n8k16.row.col.f32.bf16.bf16.f32 "
        "{%0,%1,%2,%3}, {%4,%5,%6,%7}, {%8,%9}, {%0,%1,%2,%3};"
        : "+f"(c[0]), "+f"(c[1]), "+f"(c[2]), "+f"(c[3])
        : "r"(a[0]), "r"(a[1]), "r"(a[2]), "r"(a[3]), "r"(b[0]), "r"(b[1]));
}

// ---------------------------------------------------------------------------
// Kernel 1: fp32 -> bf16 conversion + even/odd row deinterleave.
// ---------------------------------------------------------------------------
__global__ void sml_convert(const float* __restrict__ X) {
    const int i = blockIdx.x * blockDim.x + threadIdx.x;   // float4 index
    const float4 v = ((const float4*)X)[i];
    const int row = i >> 6;
    const int k4  = i & 63;
    const int p   = row >> 1;
    __nv_bfloat162 lo = __float22bfloat162_rn(make_float2(v.x, v.y));
    __nv_bfloat162 hi = __float22bfloat162_rn(make_float2(v.z, v.w));
    __nv_bfloat16* dst = (row & 1) ? g_Bbf : g_Abf;
    uint2 packed;
    packed.x = *(uint32_t*)&lo;
    packed.y = *(uint32_t*)&hi;
    *(uint2*)&dst[p * DFEAT + k4 * 4] = packed;
}

// ---------------------------------------------------------------------------
// Kernel 2: 128x256 tile of E = Aeven . Bodd^T, mma.sync, fused exp epilogue.
// 512 threads = 16 warps (4M x 4N), warp tile 32x64. Single wave (128 CTAs).
// ---------------------------------------------------------------------------
__global__ __launch_bounds__(512, 1)
void sml_gemm(void) {
    extern __shared__ char smem[];
    const uint32_t sbase = smem_u32(smem);
    float* rsum = (float*)(smem + SM_RS);
    float* csum = (float*)(smem + SM_CS);

    const int tid = threadIdx.x;
    const int wid = tid >> 5;
    const int l   = tid & 31;
    const int wm  = wid & 3;      // M band of 32
    const int wn  = wid >> 2;     // N band of 64 (of 256)
    const int bx = blockIdx.x, by = blockIdx.y;
    const int r0 = by * BTM, c0 = bx * BTN;

    if (tid < 128) rsum[tid] = 0.0f;
    if (tid < 256) csum[tid] = 0.0f;

    // ---- load tiles (bf16) into padded smem ----
    // A: 4096 uint4 slots (8/thread); B: 8192 (16/thread)
#pragma unroll
    for (int i = 0; i < 8; i++) {
        const int idx = tid + i * 512;
        const int row = idx >> 5, k4 = idx & 31;
        uint4 a = *(const uint4*)&g_Abf[(r0 + row) * DFEAT + k4 * 8];
        *(uint4*)(smem + SM_A + row * ROWB + k4 * 16) = a;
    }
#pragma unroll
    for (int i = 0; i < 16; i++) {
        const int idx = tid + i * 512;
        const int row = idx >> 5, k4 = idx & 31;
        uint4 b = *(const uint4*)&g_Bbf[(c0 + row) * DFEAT + k4 * 8];
        *(uint4*)(smem + SM_B + row * ROWB + k4 * 16) = b;
    }
    __syncthreads();

    // ---- per-lane ldmatrix address components (same as validated round-4) ----
    const int a_row = (l & 7) + 8 * ((l >> 3) & 1);
    const int a_kb  = 16 * ((l >> 4) & 1);
    const int b_row = (l & 7) + 8 * ((l >> 4) & 1);
    const int b_kb  = 16 * ((l >> 3) & 1);

    const uint32_t aAddr0 = sbase + SM_A + (uint32_t)(wm * 32 + a_row) * ROWB + a_kb;
    const uint32_t bAddr0 = sbase + SM_B + (uint32_t)(wn * 64 + b_row) * ROWB + b_kb;

    float acc[2][8][4];
#pragma unroll
    for (int mt = 0; mt < 2; mt++)
#pragma unroll
        for (int nt = 0; nt < 8; nt++)
#pragma unroll
            for (int r = 0; r < 4; r++) acc[mt][nt][r] = 0.0f;

    // ---- mainloop over K (16 steps of 16) ----
#pragma unroll
    for (int ks = 0; ks < 16; ks++) {
        const uint32_t koff = (uint32_t)ks * 32;
        uint32_t a[2][4];
        ldsm_x4(a[0], aAddr0 + koff);
        ldsm_x4(a[1], aAddr0 + 16 * ROWB + koff);
        uint32_t b[8][2];
#pragma unroll
        for (int q = 0; q < 4; q++) {
            uint32_t t[4];
            ldsm_x4(t, bAddr0 + (uint32_t)(q * 16) * ROWB + koff);
            b[2 * q][0] = t[0];      b[2 * q][1] = t[1];
            b[2 * q + 1][0] = t[2];  b[2 * q + 1][1] = t[3];
        }
#pragma unroll
        for (int mt = 0; mt < 2; mt++)
#pragma unroll
            for (int nt = 0; nt < 8; nt++)
                mma16816(acc[mt][nt], a[mt], b[nt]);
    }

    // ---- epilogue: exp, masked row/col partials, Dpos ----
    float rowp[2][2];
    float colp[8][2];
#pragma unroll
    for (int mt = 0; mt < 2; mt++)
#pragma unroll
        for (int h = 0; h < 2; h++) rowp[mt][h] = 0.0f;
#pragma unroll
    for (int nt = 0; nt < 8; nt++)
#pragma unroll
        for (int j = 0; j < 2; j++) colp[nt][j] = 0.0f;

#pragma unroll
    for (int mt = 0; mt < 2; mt++) {
#pragma unroll
        for (int h = 0; h < 2; h++) {
            const int gr = r0 + wm * 32 + mt * 16 + h * 8 + (l >> 2);
            const int rexcl = 2 * gr + 1;
#pragma unroll
            for (int nt = 0; nt < 8; nt++) {
#pragma unroll
                for (int j = 0; j < 2; j++) {
                    const int gc = c0 + wn * 64 + nt * 8 + 2 * (l & 3) + j;
                    const float e = acc[mt][nt][2 * h + j] * (1.0f / 128.0f);
                    const float x = __expf(1.0f + e);
                    if (gc != rexcl)  rowp[mt][h] += x;
                    if (gr != 2 * gc) colp[nt][j] += x;
                    if (gr == gc)     g_Dpos[gr] = e;
                }
            }
        }
    }

    // row sums: reduce across lane quads, then smem atomics (4-way contention)
#pragma unroll
    for (int mt = 0; mt < 2; mt++) {
#pragma unroll
        for (int h = 0; h < 2; h++) {
            float v = rowp[mt][h];
            v += __shfl_xor_sync(0xFFFFFFFFu, v, 1);
            v += __shfl_xor_sync(0xFFFFFFFFu, v, 2);
            if ((l & 3) == 0)
                atomicAdd(&rsum[wm * 32 + mt * 16 + h * 8 + (l >> 2)], v);
        }
    }
    // col sums
#pragma unroll
    for (int nt = 0; nt < 8; nt++) {
#pragma unroll
        for (int j = 0; j < 2; j++) {
            float v = colp[nt][j];
            v += __shfl_xor_sync(0xFFFFFFFFu, v, 4);
            v += __shfl_xor_sync(0xFFFFFFFFu, v, 8);
            v += __shfl_xor_sync(0xFFFFFFFFu, v, 16);
            if ((l >> 2) == 0)
                atomicAdd(&csum[wn * 64 + nt * 8 + 2 * (l & 3) + j], v);
        }
    }
    __syncthreads();

    if (tid < 128) {
        g_RowP[bx][r0 + tid] = rsum[tid];
    } else if (tid < 384) {
        g_ColP[by][c0 + tid - 128] = csum[tid - 128];
    }
}

// ---------------------------------------------------------------------------
// Kernel 3: finalize.
// ---------------------------------------------------------------------------
__global__ void sml_finalize(float* __restrict__ out) {
    __shared__ float red[1024];
    const int tid = threadIdx.x;
    float acc = 0.0f;
#pragma unroll
    for (int rep = 0; rep < 2; rep++) {
        const int p = tid + rep * 1024;
        float rs = 0.0f, cs = 0.0f;
#pragma unroll
        for (int s = 0; s < NBX; s++) rs += g_RowP[s][p];
#pragma unroll
        for (int s = 0; s < NBY; s++) cs += g_ColP[s][p];
        const float J = logf(1e-8f + rs + cs) - g_Dpos[p];
        const float t = fmaxf(J, 0.0f);
        acc += t * t;
    }
    red[tid] = acc;
    __syncthreads();
    for (int off = 512; off > 0; off >>= 1) {
        if (tid < off) red[tid] += red[tid + off];
        __syncthreads();
    }
    if (tid == 0) out[0] = red[0] * (1.0f / 4096.0f);
}

// ---------------------------------------------------------------------------
extern "C" void kernel_launch(void* const* d_in, const int* in_sizes, int n_in,
                              void* d_out, int out_size) {
    const float* X = (const float*)d_in[0];
    float* out = (float*)d_out;

    sml_convert<<<1024, 256>>>(X);

    cudaFuncSetAttribute(sml_gemm, cudaFuncAttributeMaxDynamicSharedMemorySize,
                         SMEM_TOTAL);
    dim3 grid(NBX, NBY);   // 8 x 16 = 128 CTAs, single wave
    sml_gemm<<<grid, 512, SMEM_TOTAL>>>();

    sml_finalize<<<1, 1024>>>(out);
}